// round 6
// baseline (speedup 1.0000x reference)
#include <cuda_runtime.h>
#include <cuda_bf16.h>

// Plane2Depth: out[b,0,H,W] = 1 / max( s*(p*u + q*v + r), 0.1 )
// where [p,q,r,s] = Wmat @ feat[b,:,H/4,W/4],
//       u = ((W%4)-1.5)/4, v = ((H%4)-1.5)/4.
// The reference's norm = sqrt(p^2+q^2+r^2+eps) cancels algebraically.
//
// R5: issue-count diet.
//  - grid = (IN_H, BATCH), block = IN_W  -> zero div/mod index math
//  - W loaded as 4x LDG.128 (was 16 scalar LDG)
//  - s folded into p,q,r: per output element only FADD + FMNMX + MUFU.RCP
//  - store offsets j*OUT_HW are compile-time immediates in STG [R+imm]

#define IN_H   192
#define IN_W   192
#define BATCH  16
#define OUT_HW 768          // 192*4
#define PLANE  (IN_H * IN_W)

__global__ __launch_bounds__(IN_W)
void plane2depth_kernel(const float* __restrict__ feat,
                        const float4* __restrict__ Wmat,
                        float* __restrict__ out)
{
    const int w = threadIdx.x;      // input column (0..191)
    const int h = blockIdx.x;       // input row
    const int b = blockIdx.y;       // batch

    // ---- load 4 channels of this pixel (each warp-coalesced 128B) ----
    const float* fp = feat + (size_t)b * 4 * PLANE + (size_t)h * IN_W + w;
    float f0 = fp[0];
    float f1 = fp[PLANE];
    float f2 = fp[2 * PLANE];
    float f3 = fp[3 * PLANE];

    // ---- W matrix: 4 vector loads, uniform broadcast, L1-resident ----
    float4 r0 = __ldg(Wmat + 0);   // w00..w03
    float4 r1 = __ldg(Wmat + 1);   // w10..w13
    float4 r2 = __ldg(Wmat + 2);   // w20..w23
    float4 r3 = __ldg(Wmat + 3);   // w30..w33

    float p = fmaf(r0.x, f0, fmaf(r0.y, f1, fmaf(r0.z, f2, r0.w * f3)));
    float q = fmaf(r1.x, f0, fmaf(r1.y, f1, fmaf(r1.z, f2, r1.w * f3)));
    float r = fmaf(r2.x, f0, fmaf(r2.y, f1, fmaf(r2.z, f2, r2.w * f3)));
    float s = fmaf(r3.x, f0, fmaf(r3.y, f1, fmaf(r3.z, f2, r3.w * f3)));

    // fold s: d = sp*u + sq*v + sr  ==  s*(p*u + q*v + r)
    float sp = s * p;
    float sq = s * q;
    float sr = s * r;

    const float UV[4] = { -0.375f, -0.125f, 0.125f, 0.375f };
    const float DMIN  = 0.1f;   // 1.0 / MAX_DEPTH

    // 4 u-terms, shared across the 4 output rows
    float spu0 = sp * UV[0], spu1 = sp * UV[1], spu2 = sp * UV[2], spu3 = sp * UV[3];

    float* obase = out + (size_t)b * OUT_HW * OUT_HW
                       + (size_t)(4 * h) * OUT_HW
                       + (size_t)(4 * w);

#pragma unroll
    for (int j = 0; j < 4; j++) {            // output sub-row (v index)
        float base = fmaf(sq, UV[j], sr);
        float4 o;
        float d;
        d = spu0 + base; d = fmaxf(d, DMIN); o.x = __fdividef(1.0f, d);
        d = spu1 + base; d = fmaxf(d, DMIN); o.y = __fdividef(1.0f, d);
        d = spu2 + base; d = fmaxf(d, DMIN); o.z = __fdividef(1.0f, d);
        d = spu3 + base; d = fmaxf(d, DMIN); o.w = __fdividef(1.0f, d);
        *(float4*)(obase + j * OUT_HW) = o;   // warp-contiguous 512B, imm offset
    }
}

extern "C" void kernel_launch(void* const* d_in, const int* in_sizes, int n_in,
                              void* d_out, int out_size)
{
    const float*  feat = (const float*)d_in[0];    // (16,4,192,192) f32
    const float4* Wmat = (const float4*)d_in[1];   // (4,4) f32
    float* out = (float*)d_out;                    // (16,1,768,768) f32

    dim3 grid(IN_H, BATCH);      // 192 x 16 = 3072 blocks
    dim3 block(IN_W);            // 192 threads = one input row
    plane2depth_kernel<<<grid, block>>>(feat, Wmat, out);
}

// round 7
// speedup vs baseline: 1.0029x; 1.0029x over previous
#include <cuda_runtime.h>
#include <cuda_bf16.h>

// Plane2Depth: out[b,0,H,W] = 1 / max( s*(p*u + q*v + r), 0.1 )
// where [p,q,r,s] = Wmat @ feat[b,:,H/4,W/4],
//       u = ((W%4)-1.5)/4, v = ((H%4)-1.5)/4.
// The reference's norm = sqrt(p^2+q^2+r^2+eps) cancels algebraically.
//
// R6: exposed-latency fix — 2 input pixels per thread (rows h and h+96,
// same column). 8 independent LDGs in flight, two independent
// compute/MUFU/store streams per warp. Indexing stays div/mod-free.

#define IN_H   192
#define IN_W   192
#define BATCH  16
#define OUT_HW 768          // 192*4
#define PLANE  (IN_H * IN_W)
#define ROWS_SPLIT (IN_H / 2)   // 96

__global__ __launch_bounds__(IN_W)
void plane2depth_kernel(const float* __restrict__ feat,
                        const float4* __restrict__ Wmat,
                        float* __restrict__ out)
{
    const int w = threadIdx.x;      // input column (0..191)
    const int h = blockIdx.x;       // input row for pixel A (0..95)
    const int b = blockIdx.y;       // batch

    // ---- 8 independent channel loads: pixel A (row h), pixel B (row h+96) ----
    const float* fpA = feat + (size_t)b * 4 * PLANE + (size_t)h * IN_W + w;
    const float* fpB = fpA + (size_t)ROWS_SPLIT * IN_W;
    float a0 = fpA[0];
    float a1 = fpA[PLANE];
    float a2 = fpA[2 * PLANE];
    float a3 = fpA[3 * PLANE];
    float b0 = fpB[0];
    float b1 = fpB[PLANE];
    float b2 = fpB[2 * PLANE];
    float b3 = fpB[3 * PLANE];

    // ---- W matrix: 4 vector loads, uniform broadcast, L1-resident ----
    float4 r0 = __ldg(Wmat + 0);
    float4 r1 = __ldg(Wmat + 1);
    float4 r2 = __ldg(Wmat + 2);
    float4 r3 = __ldg(Wmat + 3);

    // ---- matvec for both pixels (independent chains) ----
    float pA = fmaf(r0.x, a0, fmaf(r0.y, a1, fmaf(r0.z, a2, r0.w * a3)));
    float pB = fmaf(r0.x, b0, fmaf(r0.y, b1, fmaf(r0.z, b2, r0.w * b3)));
    float qA = fmaf(r1.x, a0, fmaf(r1.y, a1, fmaf(r1.z, a2, r1.w * a3)));
    float qB = fmaf(r1.x, b0, fmaf(r1.y, b1, fmaf(r1.z, b2, r1.w * b3)));
    float rA = fmaf(r2.x, a0, fmaf(r2.y, a1, fmaf(r2.z, a2, r2.w * a3)));
    float rB = fmaf(r2.x, b0, fmaf(r2.y, b1, fmaf(r2.z, b2, r2.w * b3)));
    float sA = fmaf(r3.x, a0, fmaf(r3.y, a1, fmaf(r3.z, a2, r3.w * a3)));
    float sB = fmaf(r3.x, b0, fmaf(r3.y, b1, fmaf(r3.z, b2, r3.w * b3)));

    // fold s: d = sp*u + sq*v + sr
    float spA = sA * pA, sqA = sA * qA, srA = sA * rA;
    float spB = sB * pB, sqB = sB * qB, srB = sB * rB;

    const float UV[4] = { -0.375f, -0.125f, 0.125f, 0.375f };
    const float DMIN  = 0.1f;   // 1.0 / MAX_DEPTH

    float puA[4], puB[4];
#pragma unroll
    for (int i = 0; i < 4; i++) { puA[i] = spA * UV[i]; puB[i] = spB * UV[i]; }

    float* oA = out + (size_t)b * OUT_HW * OUT_HW
                    + (size_t)(4 * h) * OUT_HW
                    + (size_t)(4 * w);
    float* oB = oA + (size_t)(4 * ROWS_SPLIT) * OUT_HW;

#pragma unroll
    for (int j = 0; j < 4; j++) {            // output sub-row (v index)
        float baseA = fmaf(sqA, UV[j], srA);
        float baseB = fmaf(sqB, UV[j], srB);
        float4 vA, vB;
        float d;
        d = puA[0] + baseA; d = fmaxf(d, DMIN); vA.x = __fdividef(1.0f, d);
        d = puB[0] + baseB; d = fmaxf(d, DMIN); vB.x = __fdividef(1.0f, d);
        d = puA[1] + baseA; d = fmaxf(d, DMIN); vA.y = __fdividef(1.0f, d);
        d = puB[1] + baseB; d = fmaxf(d, DMIN); vB.y = __fdividef(1.0f, d);
        d = puA[2] + baseA; d = fmaxf(d, DMIN); vA.z = __fdividef(1.0f, d);
        d = puB[2] + baseB; d = fmaxf(d, DMIN); vB.z = __fdividef(1.0f, d);
        d = puA[3] + baseA; d = fmaxf(d, DMIN); vA.w = __fdividef(1.0f, d);
        d = puB[3] + baseB; d = fmaxf(d, DMIN); vB.w = __fdividef(1.0f, d);
        *(float4*)(oA + j * OUT_HW) = vA;    // warp-contiguous 512B
        *(float4*)(oB + j * OUT_HW) = vB;    // warp-contiguous 512B
    }
}

extern "C" void kernel_launch(void* const* d_in, const int* in_sizes, int n_in,
                              void* d_out, int out_size)
{
    const float*  feat = (const float*)d_in[0];    // (16,4,192,192) f32
    const float4* Wmat = (const float4*)d_in[1];   // (4,4) f32
    float* out = (float*)d_out;                    // (16,1,768,768) f32

    dim3 grid(ROWS_SPLIT, BATCH);   // 96 x 16 = 1536 blocks
    dim3 block(IN_W);               // 192 threads, 2 pixels each
    plane2depth_kernel<<<grid, block>>>(feat, Wmat, out);
}

// round 8
// speedup vs baseline: 1.0269x; 1.0239x over previous
#include <cuda_runtime.h>
#include <cuda_bf16.h>
#include <cstdint>

// Plane2Depth: out[b,0,H,W] = 1 / max( s*(p*u + q*v + r), 0.1 )
// [p,q,r,s] = Wmat @ feat[b,:,H/4,W/4];  norm cancels algebraically.
//
// R7: bypass the per-thread STG path. Each block = one input row (192 px).
// Its 16 output sub-rows (4 rows x 768 floats) are 12288 CONTIGUOUS bytes in
// GMEM. Compute into SMEM (cheap STS.128), then one cp.async.bulk
// shared->global moves the whole block via the TMA/bulk engine — zero STG
// wavefronts, zero 12-cyc STG.128 issue costs on the LSU.

#define IN_H   192
#define IN_W   192
#define BATCH  16
#define OUT_HW 768          // 192*4
#define PLANE  (IN_H * IN_W)
#define TILE_BYTES (4 * OUT_HW * 4)   // 12288

__global__ __launch_bounds__(IN_W)
void plane2depth_kernel(const float* __restrict__ feat,
                        const float4* __restrict__ Wmat,
                        float* __restrict__ out)
{
    __shared__ __align__(16) float sm[4][OUT_HW];   // 12288 B

    const int w = threadIdx.x;      // input column (0..191)
    const int h = blockIdx.x;       // input row
    const int b = blockIdx.y;       // batch

    // ---- load 4 channels of this pixel (each warp-coalesced 128B) ----
    const float* fp = feat + (size_t)b * 4 * PLANE + (size_t)h * IN_W + w;
    float f0 = fp[0];
    float f1 = fp[PLANE];
    float f2 = fp[2 * PLANE];
    float f3 = fp[3 * PLANE];

    // ---- W matrix: 4 vector loads, uniform broadcast, L1-resident ----
    float4 r0 = __ldg(Wmat + 0);
    float4 r1 = __ldg(Wmat + 1);
    float4 r2 = __ldg(Wmat + 2);
    float4 r3 = __ldg(Wmat + 3);

    float p = fmaf(r0.x, f0, fmaf(r0.y, f1, fmaf(r0.z, f2, r0.w * f3)));
    float q = fmaf(r1.x, f0, fmaf(r1.y, f1, fmaf(r1.z, f2, r1.w * f3)));
    float r = fmaf(r2.x, f0, fmaf(r2.y, f1, fmaf(r2.z, f2, r2.w * f3)));
    float s = fmaf(r3.x, f0, fmaf(r3.y, f1, fmaf(r3.z, f2, r3.w * f3)));

    // fold s:  d = sp*u + sq*v + sr
    float sp = s * p, sq = s * q, sr = s * r;

    const float UV[4] = { -0.375f, -0.125f, 0.125f, 0.375f };
    const float DMIN  = 0.1f;   // 1.0 / MAX_DEPTH

    float pu0 = sp * UV[0], pu1 = sp * UV[1], pu2 = sp * UV[2], pu3 = sp * UV[3];

#pragma unroll
    for (int j = 0; j < 4; j++) {            // output sub-row (v index)
        float base = fmaf(sq, UV[j], sr);
        float4 o;
        float d;
        d = pu0 + base; d = fmaxf(d, DMIN); o.x = __fdividef(1.0f, d);
        d = pu1 + base; d = fmaxf(d, DMIN); o.y = __fdividef(1.0f, d);
        d = pu2 + base; d = fmaxf(d, DMIN); o.z = __fdividef(1.0f, d);
        d = pu3 + base; d = fmaxf(d, DMIN); o.w = __fdividef(1.0f, d);
        *(float4*)(&sm[j][4 * w]) = o;       // STS.128, conflict-free
    }

    __syncthreads();

    // One bulk copy: SMEM (12288B) -> GMEM rows [4h, 4h+4), fully contiguous.
    if (threadIdx.x == 0) {
        float* dst = out + ((size_t)b * OUT_HW + (size_t)(4 * h)) * OUT_HW;
        uint32_t saddr;
        asm volatile("{ .reg .u64 t; cvta.to.shared.u64 t, %1; cvt.u32.u64 %0, t; }"
                     : "=r"(saddr) : "l"(&sm[0][0]));
        asm volatile("cp.async.bulk.global.shared::cta.bulk_group [%0], [%1], %2;"
                     :: "l"(dst), "r"(saddr), "r"((int)TILE_BYTES) : "memory");
        asm volatile("cp.async.bulk.commit_group;" ::: "memory");
        asm volatile("cp.async.bulk.wait_group 0;" ::: "memory");
    }

    // keep SMEM alive until the bulk engine has consumed it
    __syncthreads();
}

extern "C" void kernel_launch(void* const* d_in, const int* in_sizes, int n_in,
                              void* d_out, int out_size)
{
    const float*  feat = (const float*)d_in[0];    // (16,4,192,192) f32
    const float4* Wmat = (const float4*)d_in[1];   // (4,4) f32
    float* out = (float*)d_out;                    // (16,1,768,768) f32

    dim3 grid(IN_H, BATCH);      // 192 x 16 = 3072 blocks
    dim3 block(IN_W);            // 192 threads = one input row
    plane2depth_kernel<<<grid, block>>>(feat, Wmat, out);
}